// round 14
// baseline (speedup 1.0000x reference)
#include <cuda_runtime.h>
#include <cuda_fp16.h>
#include <math.h>
#include <stdint.h>

#define B 8
#define D 256
#define NN 1024
#define MM 1024
#define KD 64
#define VD 64

#define NSTAGE 4
#define CH_K 3072            // padded K chunk (halfs)
#define CH_V 2560            // padded V chunk (halfs)
#define HALF_STAGE 5632      // CH_K + CH_V
#define STAGE_H 11264        // 2 chunks = 64 m
#define STAGES_H 45056       // NSTAGE * STAGE_H
#define XS_OFF STAGES_H
#define XSP 264              // Xs [32 n][264 d] halfs
#define QSM_OFF STAGES_H
#define KP 68                // Qsm [32 nl][8 h][68 k] halfs
#define SMEM_HALFS (QSM_OFF + 32 * 8 * KP)   // 62464
#define SMEM_BYTES (SMEM_HALFS * 2)           // 124928
#define OSP 520              // epilogue Os [32 n][520 vh] @ 0

#define QSCALE 0.1803368801f   // 0.125 * log2(e)

__device__ __half g_WqP[512 * D];    // Wq A-frags fp16 (8-warp), pre-scaled
__device__ __half g_K[B * 32 * 2048];   // K as B-frags (k x m) per 32-m chunk
__device__ __half g_V[B * 32 * 2048];   // V as B-frags (m x v) per 32-m chunk
__device__ __half g_WoP[D * 512];    // Wo A-frags fp16 (8-warp)

__device__ __forceinline__ float ex2(float x) {
    float r; asm("ex2.approx.f32 %0, %1;" : "=f"(r) : "f"(x)); return r;
}
__device__ __forceinline__ float rcp(float x) {
    float r; asm("rcp.approx.f32 %0, %1;" : "=f"(r) : "f"(x)); return r;
}
__device__ __forceinline__ uint32_t packh2(float a, float b) {
    __half2 h = __floats2half2_rn(a, b);
    return *reinterpret_cast<uint32_t*>(&h);
}
__device__ __forceinline__ void mmaf16(float* c, const uint32_t* a, const uint32_t* b) {
    asm volatile(
        "mma.sync.aligned.m16n8k16.row.col.f32.f16.f16.f32 "
        "{%0,%1,%2,%3}, {%4,%5,%6,%7}, {%8,%9}, {%0,%1,%2,%3};\n"
        : "+f"(c[0]), "+f"(c[1]), "+f"(c[2]), "+f"(c[3])
        : "r"(a[0]), "r"(a[1]), "r"(a[2]), "r"(a[3]), "r"(b[0]), "r"(b[1]));
}
__device__ __forceinline__ void mmaf16z(float* c, const uint32_t* a, const uint32_t* b) {
    asm volatile(
        "mma.sync.aligned.m16n8k16.row.col.f32.f16.f16.f32 "
        "{%0,%1,%2,%3}, {%4,%5,%6,%7}, {%8,%9}, {%10,%10,%10,%10};\n"
        : "=f"(c[0]), "=f"(c[1]), "=f"(c[2]), "=f"(c[3])
        : "r"(a[0]), "r"(a[1]), "r"(a[2]), "r"(a[3]), "r"(b[0]), "r"(b[1]),
          "f"(0.0f));
}
__device__ __forceinline__ void cp16(uint32_t dst, const void* src) {
    asm volatile("cp.async.cg.shared.global [%0], [%1], 16;\n"
                 :: "r"(dst), "l"(src));
}
#define CP_COMMIT() asm volatile("cp.async.commit_group;\n" ::)
#define CP_WAIT(n)  asm volatile("cp.async.wait_group %0;\n" :: "n"(n))

// ---------------- kernel 0: pack Wq / Wo fragments ----------------
__global__ void pack_weights(const float* __restrict__ Wq,
                             const float* __restrict__ Wo) {
    int i = blockIdx.x * blockDim.x + threadIdx.x;
    if (i < 512 * D) {   // WqP: [w8][kc16][mi4][lane32][r4][dlt2]
        int dlt = i & 1, r = (i >> 1) & 3, ln = (i >> 3) & 31;
        int mi = (i >> 8) & 3, kc = (i >> 10) & 15, w = (i >> 14) & 7;
        int g = ln >> 2, t = ln & 3;
        int rk = w * 64 + mi * 16 + g + 8 * (r & 1);
        int d = kc * 16 + 2 * t + dlt + 8 * (r >> 1);
        int kq = rk >> 3, h = rk & 7;
        g_WqP[i] = __float2half_rn(Wq[h * (D * KD) + d * KD + kq] * QSCALE);
    }
    if (i < D * 512) {   // WoP: [w8][ks32][mi2][lane32][r4][dlt2]
        int dlt = i & 1, r = (i >> 1) & 3, ln = (i >> 3) & 31;
        int mi = (i >> 8) & 1, ks = (i >> 9) & 31, w = (i >> 14) & 7;
        int g = ln >> 2, t = ln & 3;
        int d = w * 32 + mi * 16 + g + 8 * (r & 1);
        int vh = ks * 16 + 2 * t + dlt + 8 * (r >> 1);
        g_WoP[i] = __float2half_rn(Wo[d * 512 + vh]);
    }
}

// ---------------- kernel 1: K/V projection GEMM, coalesced frag output ----------------
__global__ void __launch_bounds__(256) proj_kv(const float* __restrict__ Wk,
                                               const float* __restrict__ Wv,
                                               const float* __restrict__ X) {
    extern __shared__ char smraw[];
    float* As = (float*)smraw;          // [16][136]
    float* Xs = As + 16 * 136;          // [16][128]
    const int b = blockIdx.z, n0 = blockIdx.x * 128;
    const float* Xb = X + b * (D * NN);

    float acc[8][8] = {};
    const int tid = threadIdx.x;
    const int tr = tid >> 4, tn = tid & 15;

    for (int dc = 0; dc < D; dc += 16) {
#pragma unroll
        for (int i = 0; i < 8; i++) {
            int idx = tid + i * 256;
            int rr = idx >> 4, c = idx & 15;
            As[c * 136 + rr] = (rr < 64) ? Wk[(dc + c) * KD + rr]
                                         : Wv[(dc + c) * VD + (rr - 64)];
        }
#pragma unroll
        for (int i = 0; i < 8; i++) {
            int idx = tid + i * 256;
            int c = idx >> 7, nn = idx & 127;
            Xs[c * 128 + nn] = Xb[(dc + c) * NN + n0 + nn];
        }
        __syncthreads();
#pragma unroll
        for (int c = 0; c < 16; c++) {
            float4 a0 = *(const float4*)&As[c * 136 + tr * 4];
            float4 a1 = *(const float4*)&As[c * 136 + 64 + tr * 4];
            float4 x0 = *(const float4*)&Xs[c * 128 + tn * 4];
            float4 x1 = *(const float4*)&Xs[c * 128 + 64 + tn * 4];
            float ra[8] = {a0.x, a0.y, a0.z, a0.w, a1.x, a1.y, a1.z, a1.w};
            float rx[8] = {x0.x, x0.y, x0.z, x0.w, x1.x, x1.y, x1.z, x1.w};
#pragma unroll
            for (int i = 0; i < 8; i++)
#pragma unroll
                for (int j = 0; j < 8; j++) acc[i][j] += ra[i] * rx[j];
        }
        __syncthreads();
    }

    // stage fp16 fragments in smem (overlay As/Xs): K [4][2048] @0, V @8192
    __half* stg = (__half*)smraw;
#pragma unroll
    for (int i = 0; i < 8; i++) {
        int r = tr * 4 + (i & 3) + (i >> 2) * 64;
#pragma unroll
        for (int j = 0; j < 8; j++) {
            int n = n0 + tn * 4 + (j & 3) + (j >> 2) * 64;
            __half v = __float2half_rn(acc[i][j]);
            int mchl = (n >> 5) & 3, ml = n & 31;
            if (r < 64) {   // K B-frag: K[k][m]
                int k = r;
                int nt = ml >> 3, gd = ml & 7;
                int ks = k >> 4, k16 = k & 15;
                int e = k16 >> 3, rem = k16 & 7, tg = rem >> 1, dlt = rem & 1;
                int ln = gd * 4 + tg;
                stg[mchl * 2048 + ks * 512 + ln * 16 + nt * 4 + e * 2 + dlt] = v;
            } else {        // V B-frag: V[m][v]
                int vv = r - 64;
                int ms = ml >> 4, m16 = ml & 15;
                int e = m16 >> 3, rem = m16 & 7, tg = rem >> 1, dlt = rem & 1;
                int vt = vv >> 3, gd = vv & 7;
                int ln = gd * 4 + tg;
                stg[8192 + mchl * 2048 + ms * 1024 + ln * 32 + vt * 4 + e * 2 + dlt] = v;
            }
        }
    }
    __syncthreads();

    // coalesced copy out: this CTA's region is contiguous (4 chunks x 2048 halfs)
    const uint4* s4 = (const uint4*)stg;
    uint4* dK4 = (uint4*)(g_K + (b * 32 + (n0 >> 5)) * 2048);
    uint4* dV4 = (uint4*)(g_V + (b * 32 + (n0 >> 5)) * 2048);
#pragma unroll
    for (int i = 0; i < 4; i++) dK4[tid + i * 256] = s4[tid + i * 256];
#pragma unroll
    for (int i = 0; i < 4; i++) dV4[tid + i * 256] = s4[1024 + tid + i * 256];
}

// phase-1 over a 64-m stage: c1[mi][c*4+nt] = logits^T
__device__ __forceinline__ void phase1_stage(const __half* stg,
                                             const uint32_t Qreg[4][2][4],
                                             float c1[2][8][4], int lane) {
#pragma unroll
    for (int c = 0; c < 2; c++) {
        const __half* Ks = stg + c * HALF_STAGE;
#pragma unroll
        for (int ks = 0; ks < 4; ks++) {
            uint4 ka = *(const uint4*)&Ks[ks * 768 + lane * 24];
            uint4 kb = *(const uint4*)&Ks[ks * 768 + lane * 24 + 8];
            uint32_t kf[4][2] = {{ka.x, ka.y}, {ka.z, ka.w},
                                 {kb.x, kb.y}, {kb.z, kb.w}};
#pragma unroll
            for (int mi = 0; mi < 2; mi++)
#pragma unroll
                for (int nt = 0; nt < 4; nt++) {
                    if (ks == 0) mmaf16z(c1[mi][c * 4 + nt], Qreg[0][mi], kf[nt]);
                    else         mmaf16(c1[mi][c * 4 + nt], Qreg[ks][mi], kf[nt]);
                }
        }
    }
}

// softmax over heads (xor 4, 8 reductions), pack to half2
__device__ __forceinline__ void softmax_pack(float c1[2][8][4],
                                             uint32_t p01[2][8], uint32_t p23[2][8]) {
#pragma unroll
    for (int mi = 0; mi < 2; mi++)
#pragma unroll
        for (int nt = 0; nt < 8; nt++) {
            float* cc = c1[mi][nt];
            float e0 = ex2(cc[0]), e1 = ex2(cc[1]);
            float e2 = ex2(cc[2]), e3 = ex2(cc[3]);
            float s02 = e0 + e2, s13 = e1 + e3;
            s02 += __shfl_xor_sync(0xffffffffu, s02, 4);
            s02 += __shfl_xor_sync(0xffffffffu, s02, 8);
            s13 += __shfl_xor_sync(0xffffffffu, s13, 4);
            s13 += __shfl_xor_sync(0xffffffffu, s13, 8);
            float r02 = rcp(s02), r13 = rcp(s13);
            p01[mi][nt] = packh2(e0 * r02, e1 * r13);
            p23[mi][nt] = packh2(e2 * r02, e3 * r13);
        }
}

// phase-3 over a 64-m stage: Oacc += attn^T x V
__device__ __forceinline__ void phase3_stage(const __half* stg,
                                             const uint32_t p01[2][8],
                                             const uint32_t p23[2][8],
                                             float Oacc[2][8][4], int lane) {
#pragma unroll
    for (int c = 0; c < 2; c++) {
        const __half* Vs = stg + c * HALF_STAGE + CH_K;
#pragma unroll
        for (int ms = 0; ms < 2; ms++) {
            uint4 va = *(const uint4*)&Vs[ms * 1280 + lane * 40];
            uint4 vb = *(const uint4*)&Vs[ms * 1280 + lane * 40 + 8];
            uint4 vc = *(const uint4*)&Vs[ms * 1280 + lane * 40 + 16];
            uint4 vd = *(const uint4*)&Vs[ms * 1280 + lane * 40 + 24];
            uint32_t vf[8][2] = {{va.x, va.y}, {va.z, va.w}, {vb.x, vb.y}, {vb.z, vb.w},
                                 {vc.x, vc.y}, {vc.z, vc.w}, {vd.x, vd.y}, {vd.z, vd.w}};
#pragma unroll
            for (int mi = 0; mi < 2; mi++) {
                uint32_t af[4] = {p01[mi][c * 4 + 2 * ms], p23[mi][c * 4 + 2 * ms],
                                  p01[mi][c * 4 + 2 * ms + 1], p23[mi][c * 4 + 2 * ms + 1]};
#pragma unroll
                for (int vt = 0; vt < 8; vt++)
                    mmaf16(Oacc[mi][vt], af, vf[vt]);
            }
        }
    }
}

// ---------------- kernel 2: fused main (256 thr, 8 warps, 64-m stages) ----------------
__global__ void __launch_bounds__(256, 1) mqa_main(const float* __restrict__ x,
                                                   float* __restrict__ out) {
    extern __shared__ char smraw[];
    __half* smh = (__half*)smraw;

    const int b = blockIdx.y;
    const int n0 = blockIdx.x * 32;
    const int tid = threadIdx.x;
    const int lane = tid & 31;
    const int wgrp = tid >> 5;   // 0..7
    const int gid = lane >> 2;
    const int tig = lane & 3;

    const __half* Kg = g_K + b * 65536;
    const __half* Vg = g_V + b * 65536;

    const int dK = (tid >> 6) * 768 + ((tid & 63) >> 1) * 24 + (tid & 1) * 8;
    const int dV = (tid >> 7) * 1280 + ((tid >> 2) & 31) * 40 + (tid & 3) * 8;
    const uint32_t smem_u32 = (uint32_t)__cvta_generic_to_shared(smh);

    // issue first 3 stages (each = 2 gmem chunks of K and V)
#pragma unroll
    for (int s = 0; s < 3; s++) {
        uint32_t base = smem_u32 + (s * STAGE_H) * 2;
        const __half* K0 = Kg + (2 * s) * 2048 + tid * 8;
        const __half* V0 = Vg + (2 * s) * 2048 + tid * 8;
        cp16(base + dK * 2, K0);
        cp16(base + (CH_K + dV) * 2, V0);
        cp16(base + (HALF_STAGE + dK) * 2, K0 + 2048);
        cp16(base + (HALF_STAGE + CH_K + dV) * 2, V0 + 2048);
        CP_COMMIT();
    }

    // ---- prologue: Q projection (fp16 mma), then Q^T A-frags ----
    uint32_t Qreg[4][2][4];
    {
        __half* Xs = smh + XS_OFF;   // [32 n][264 d]
        const float* Xb = x + b * (D * NN);
#pragma unroll
        for (int i = 0; i < 32; i++) {
            int idx = tid + i * 256;
            int dd = idx >> 5, nn2 = idx & 31;
            Xs[nn2 * XSP + dd] = __float2half_rn(Xb[dd * NN + n0 + nn2]);
        }
        __syncthreads();

        float qa[4][4][4] = {};
        const __half* WqPw = g_WqP + wgrp * 16384;
#pragma unroll 4
        for (int kc = 0; kc < 16; kc++) {
            uint32_t bf[4][2];
#pragma unroll
            for (int ni = 0; ni < 4; ni++) {
                bf[ni][0] = *(const uint32_t*)&Xs[(ni * 8 + gid) * XSP + kc * 16 + 2 * tig];
                bf[ni][1] = *(const uint32_t*)&Xs[(ni * 8 + gid) * XSP + kc * 16 + 2 * tig + 8];
            }
#pragma unroll
            for (int mi = 0; mi < 4; mi++) {
                uint4 a = *(const uint4*)&WqPw[(kc * 4 + mi) * 256 + lane * 8];
#pragma unroll
                for (int ni = 0; ni < 4; ni++)
                    mmaf16(qa[mi][ni], (const uint32_t*)&a, bf[ni]);
            }
        }
        __syncthreads();   // Xs reads done

        __half* Qsm = smh + QSM_OFF;   // [nl32][h8][KP]
#pragma unroll
        for (int mi = 0; mi < 4; mi++)
#pragma unroll
            for (int ni = 0; ni < 4; ni++)
#pragma unroll
                for (int r = 0; r < 4; r++) {
                    int rk = wgrp * 64 + mi * 16 + gid + 8 * (r >> 1);
                    int nl = ni * 8 + 2 * tig + (r & 1);
                    Qsm[(nl * 8 + (rk & 7)) * KP + (rk >> 3)] =
                        __float2half_rn(qa[mi][ni][r]);
                }
        __syncthreads();

        // A-frags: warp rows = 32 nh cols (mi 0..1), h via gid bits
#pragma unroll
        for (int ks = 0; ks < 4; ks++)
#pragma unroll
            for (int mi = 0; mi < 2; mi++) {
                int nlb = wgrp * 4 + 2 * mi + (gid >> 2);
                int r01 = (nlb * 8 + (gid & 3)) * KP;
                int r23 = (nlb * 8 + (gid & 3) + 4) * KP;
                int kk = ks * 16 + 2 * tig;
                Qreg[ks][mi][0] = *(const uint32_t*)&Qsm[r01 + kk];
                Qreg[ks][mi][1] = *(const uint32_t*)&Qsm[r23 + kk];
                Qreg[ks][mi][2] = *(const uint32_t*)&Qsm[r01 + kk + 8];
                Qreg[ks][mi][3] = *(const uint32_t*)&Qsm[r23 + kk + 8];
            }
    }

    // ---- stage 0 ready; phase1(0) ----
    CP_WAIT(2);
    __syncthreads();

    float c1[2][8][4];
    phase1_stage(smh, Qreg, c1, lane);

    float Oacc[2][8][4] = {};

#pragma unroll 1
    for (int it = 0; it < 15; it++) {
        CP_WAIT(1);
        __syncthreads();

        if (it + 3 < 16) {
            int st = it + 3;
            uint32_t base = smem_u32 + ((st & 3) * STAGE_H) * 2;
            const __half* K0 = Kg + (2 * st) * 2048 + tid * 8;
            const __half* V0 = Vg + (2 * st) * 2048 + tid * 8;
            cp16(base + dK * 2, K0);
            cp16(base + (CH_K + dV) * 2, V0);
            cp16(base + (HALF_STAGE + dK) * 2, K0 + 2048);
            cp16(base + (HALF_STAGE + CH_K + dV) * 2, V0 + 2048);
        }
        CP_COMMIT();

        uint32_t p01[2][8], p23[2][8];
        softmax_pack(c1, p01, p23);

        // phase1 of next stage fills softmax stall holes (c1 consumed)
        phase1_stage(smh + ((it + 1) & 3) * STAGE_H, Qreg, c1, lane);

        phase3_stage(smh + (it & 3) * STAGE_H, p01, p23, Oacc, lane);
    }

    // peeled final stage (it = 15)
    {
        CP_WAIT(0);
        __syncthreads();
        uint32_t p01[2][8], p23[2][8];
        softmax_pack(c1, p01, p23);
        phase3_stage(smh + 3 * STAGE_H, p01, p23, Oacc, lane);
    }
    __syncthreads();

    // ---- epilogue: stage O^T C-frags into Os[n][vh] ----
    __half* Os = smh;   // [32][OSP]
#pragma unroll
    for (int mi = 0; mi < 2; mi++) {
        int nl = wgrp * 4 + 2 * mi + (gid >> 2);
        int hb = gid & 3;
#pragma unroll
        for (int vt = 0; vt < 8; vt++) {
            int v0 = vt * 8 + 2 * tig;
            Os[nl * OSP + v0 * 8 + hb]           = __float2half_rn(Oacc[mi][vt][0]);
            Os[nl * OSP + (v0 + 1) * 8 + hb]     = __float2half_rn(Oacc[mi][vt][1]);
            Os[nl * OSP + v0 * 8 + hb + 4]       = __float2half_rn(Oacc[mi][vt][2]);
            Os[nl * OSP + (v0 + 1) * 8 + hb + 4] = __float2half_rn(Oacc[mi][vt][3]);
        }
    }
    __syncthreads();

    // ---- res = Wo @ O (fp16 mma, Wo A-frags from gmem/L2) ----
    float racc[2][4][4] = {};
    const __half* WoP = g_WoP + wgrp * 16384;
#pragma unroll 2
    for (int ks = 0; ks < 32; ks++) {
        uint4 a0 = *(const uint4*)&WoP[(ks * 2 + 0) * 256 + lane * 8];
        uint4 a1 = *(const uint4*)&WoP[(ks * 2 + 1) * 256 + lane * 8];
#pragma unroll
        for (int ni = 0; ni < 4; ni++) {
            uint32_t bf[2];
            bf[0] = *(const uint32_t*)&Os[(ni * 8 + gid) * OSP + ks * 16 + 2 * tig];
            bf[1] = *(const uint32_t*)&Os[(ni * 8 + gid) * OSP + ks * 16 + 2 * tig + 8];
            mmaf16(racc[0][ni], (const uint32_t*)&a0, bf);
            mmaf16(racc[1][ni], (const uint32_t*)&a1, bf);
        }
    }

    float* ob = out + b * (D * NN);
#pragma unroll
    for (int mi = 0; mi < 2; mi++)
#pragma unroll
        for (int ni = 0; ni < 4; ni++) {
            int d = wgrp * 32 + mi * 16 + gid;
            *(float2*)&ob[d * NN + n0 + ni * 8 + tig * 2] =
                make_float2(racc[mi][ni][0], racc[mi][ni][1]);
            *(float2*)&ob[(d + 8) * NN + n0 + ni * 8 + tig * 2] =
                make_float2(racc[mi][ni][2], racc[mi][ni][3]);
        }
}

// ---------------- launcher ----------------
extern "C" void kernel_launch(void* const* d_in, const int* in_sizes, int n_in,
                              void* d_out, int out_size) {
    const float* x     = (const float*)d_in[0];
    const float* value = (const float*)d_in[1];
    const float* Wq    = (const float*)d_in[2];
    const float* Wk    = (const float*)d_in[3];
    const float* Wv    = (const float*)d_in[4];
    const float* Wo    = (const float*)d_in[5];
    float* out = (float*)d_out;

    pack_weights<<<512, 256>>>(Wq, Wo);
    proj_kv<<<dim3(MM / 128, 1, B), 256, 32768>>>(Wk, Wv, value);

    cudaFuncSetAttribute(mqa_main, cudaFuncAttributeMaxDynamicSharedMemorySize, SMEM_BYTES);
    mqa_main<<<dim3(NN / 32, B), 256, SMEM_BYTES>>>(x, out);
}

// round 15
// speedup vs baseline: 1.0225x; 1.0225x over previous
#include <cuda_runtime.h>
#include <cuda_fp16.h>
#include <math.h>
#include <stdint.h>

#define B 8
#define D 256
#define NN 1024
#define MM 1024
#define KD 64
#define VD 64

#define NSTAGE 5
// smem halves: stage = K(3072, padded) + V(2560, padded)
#define STAGE_H 5632
#define V_OFF   3072
#define STAGES_H (NSTAGE * STAGE_H)     // 28160
#define XS_OFF  STAGES_H
#define XSP 264                          // Xs [32 n][264 d]
#define QSM_OFF STAGES_H
#define KP 68                            // Qsm [32 nl][8 h][68 k]
#define SMEM_HALFS (QSM_OFF + 32 * 8 * KP)   // 45568
#define SMEM_BYTES (SMEM_HALFS * 2)           // 91136
#define OSP 520                          // epilogue Os [32 n][520 vh] @ 0

#define QSCALE 0.1803368801f   // 0.125 * log2(e)

__device__ __half g_WqP[512 * D];    // Wq A-frags fp16 (8-warp), pre-scaled
__device__ __half g_K[B * 32 * 2048];   // K as B-frags (k x m) per chunk
__device__ __half g_V[B * 32 * 2048];   // V as B-frags (m x v) per chunk
__device__ __half g_WoP[D * 512];    // Wo A-frags fp16 (8-warp)

__device__ __forceinline__ uint32_t h2u(__half2 h) {
    return *reinterpret_cast<uint32_t*>(&h);
}
__device__ __forceinline__ __half2 u2h(uint32_t u) {
    return *reinterpret_cast<__half2*>(&u);
}
__device__ __forceinline__ void mmaf16(float* c, const uint32_t* a, const uint32_t* b) {
    asm volatile(
        "mma.sync.aligned.m16n8k16.row.col.f32.f16.f16.f32 "
        "{%0,%1,%2,%3}, {%4,%5,%6,%7}, {%8,%9}, {%0,%1,%2,%3};\n"
        : "+f"(c[0]), "+f"(c[1]), "+f"(c[2]), "+f"(c[3])
        : "r"(a[0]), "r"(a[1]), "r"(a[2]), "r"(a[3]), "r"(b[0]), "r"(b[1]));
}
__device__ __forceinline__ void mmaf16z(float* c, const uint32_t* a, const uint32_t* b) {
    asm volatile(
        "mma.sync.aligned.m16n8k16.row.col.f32.f16.f16.f32 "
        "{%0,%1,%2,%3}, {%4,%5,%6,%7}, {%8,%9}, {%10,%10,%10,%10};\n"
        : "=f"(c[0]), "=f"(c[1]), "=f"(c[2]), "=f"(c[3])
        : "r"(a[0]), "r"(a[1]), "r"(a[2]), "r"(a[3]), "r"(b[0]), "r"(b[1]),
          "f"(0.0f));
}
__device__ __forceinline__ void cp16(uint32_t dst, const void* src) {
    asm volatile("cp.async.cg.shared.global [%0], [%1], 16;\n"
                 :: "r"(dst), "l"(src));
}
#define CP_COMMIT() asm volatile("cp.async.commit_group;\n" ::)
#define CP_WAIT(n)  asm volatile("cp.async.wait_group %0;\n" :: "n"(n))

// ---------------- kernel 0: pack Wq / Wo fragments ----------------
__global__ void pack_weights(const float* __restrict__ Wq,
                             const float* __restrict__ Wo) {
    int i = blockIdx.x * blockDim.x + threadIdx.x;
    if (i < 512 * D) {   // WqP: [w8][kc16][mi4][lane32][r4][dlt2]
        int dlt = i & 1, r = (i >> 1) & 3, ln = (i >> 3) & 31;
        int mi = (i >> 8) & 3, kc = (i >> 10) & 15, w = (i >> 14) & 7;
        int g = ln >> 2, t = ln & 3;
        int rk = w * 64 + mi * 16 + g + 8 * (r & 1);
        int d = kc * 16 + 2 * t + dlt + 8 * (r >> 1);
        int kq = rk >> 3, h = rk & 7;
        g_WqP[i] = __float2half_rn(Wq[h * (D * KD) + d * KD + kq] * QSCALE);
    }
    if (i < D * 512) {   // WoP: [w8][ks32][mi2][lane32][r4][dlt2]
        int dlt = i & 1, r = (i >> 1) & 3, ln = (i >> 3) & 31;
        int mi = (i >> 8) & 1, ks = (i >> 9) & 31, w = (i >> 14) & 7;
        int g = ln >> 2, t = ln & 3;
        int d = w * 32 + mi * 16 + g + 8 * (r & 1);
        int vh = ks * 16 + 2 * t + dlt + 8 * (r >> 1);
        g_WoP[i] = __float2half_rn(Wo[d * 512 + vh]);
    }
}

// ---------------- kernel 1: K/V projection GEMM, coalesced frag output ----------------
__global__ void __launch_bounds__(256) proj_kv(const float* __restrict__ Wk,
                                               const float* __restrict__ Wv,
                                               const float* __restrict__ X) {
    extern __shared__ char smraw[];
    float* As = (float*)smraw;          // [16][136]
    float* Xs = As + 16 * 136;          // [16][128]
    const int b = blockIdx.z, n0 = blockIdx.x * 128;
    const float* Xb = X + b * (D * NN);

    float acc[8][8] = {};
    const int tid = threadIdx.x;
    const int tr = tid >> 4, tn = tid & 15;

    for (int dc = 0; dc < D; dc += 16) {
#pragma unroll
        for (int i = 0; i < 8; i++) {
            int idx = tid + i * 256;
            int rr = idx >> 4, c = idx & 15;
            As[c * 136 + rr] = (rr < 64) ? Wk[(dc + c) * KD + rr]
                                         : Wv[(dc + c) * VD + (rr - 64)];
        }
#pragma unroll
        for (int i = 0; i < 8; i++) {
            int idx = tid + i * 256;
            int c = idx >> 7, nn = idx & 127;
            Xs[c * 128 + nn] = Xb[(dc + c) * NN + n0 + nn];
        }
        __syncthreads();
#pragma unroll
        for (int c = 0; c < 16; c++) {
            float4 a0 = *(const float4*)&As[c * 136 + tr * 4];
            float4 a1 = *(const float4*)&As[c * 136 + 64 + tr * 4];
            float4 x0 = *(const float4*)&Xs[c * 128 + tn * 4];
            float4 x1 = *(const float4*)&Xs[c * 128 + 64 + tn * 4];
            float ra[8] = {a0.x, a0.y, a0.z, a0.w, a1.x, a1.y, a1.z, a1.w};
            float rx[8] = {x0.x, x0.y, x0.z, x0.w, x1.x, x1.y, x1.z, x1.w};
#pragma unroll
            for (int i = 0; i < 8; i++)
#pragma unroll
                for (int j = 0; j < 8; j++) acc[i][j] += ra[i] * rx[j];
        }
        __syncthreads();
    }

    // stage fp16 fragments in smem (overlay As/Xs): K [4][2048] @0, V @8192
    __half* stg = (__half*)smraw;
#pragma unroll
    for (int i = 0; i < 8; i++) {
        int r = tr * 4 + (i & 3) + (i >> 2) * 64;
#pragma unroll
        for (int j = 0; j < 8; j++) {
            int n = n0 + tn * 4 + (j & 3) + (j >> 2) * 64;
            __half v = __float2half_rn(acc[i][j]);
            int mchl = (n >> 5) & 3, ml = n & 31;
            if (r < 64) {   // K B-frag: K[k][m]
                int k = r;
                int nt = ml >> 3, gd = ml & 7;
                int ks = k >> 4, k16 = k & 15;
                int e = k16 >> 3, rem = k16 & 7, tg = rem >> 1, dlt = rem & 1;
                int ln = gd * 4 + tg;
                stg[mchl * 2048 + ks * 512 + ln * 16 + nt * 4 + e * 2 + dlt] = v;
            } else {        // V B-frag: V[m][v]
                int vv = r - 64;
                int ms = ml >> 4, m16 = ml & 15;
                int e = m16 >> 3, rem = m16 & 7, tg = rem >> 1, dlt = rem & 1;
                int vt = vv >> 3, gd = vv & 7;
                int ln = gd * 4 + tg;
                stg[8192 + mchl * 2048 + ms * 1024 + ln * 32 + vt * 4 + e * 2 + dlt] = v;
            }
        }
    }
    __syncthreads();

    // coalesced copy out: this CTA's region is contiguous (4 chunks x 2048 halfs)
    const uint4* s4 = (const uint4*)stg;
    uint4* dK4 = (uint4*)(g_K + (b * 32 + (n0 >> 5)) * 2048);
    uint4* dV4 = (uint4*)(g_V + (b * 32 + (n0 >> 5)) * 2048);
#pragma unroll
    for (int i = 0; i < 4; i++) dK4[tid + i * 256] = s4[tid + i * 256];
#pragma unroll
    for (int i = 0; i < 4; i++) dV4[tid + i * 256] = s4[1024 + tid + i * 256];
}

// phase-1: c1[mi][nt] = logits^T  (A = Q^T regs, B = K from smem)
__device__ __forceinline__ void phase1(const __half* Ks,
                                       const uint32_t Qreg[4][2][4],
                                       float c1[2][4][4], int lane) {
#pragma unroll
    for (int ks = 0; ks < 4; ks++) {
        uint4 ka = *(const uint4*)&Ks[ks * 768 + lane * 24];
        uint4 kb = *(const uint4*)&Ks[ks * 768 + lane * 24 + 8];
        uint32_t kf[4][2] = {{ka.x, ka.y}, {ka.z, ka.w}, {kb.x, kb.y}, {kb.z, kb.w}};
#pragma unroll
        for (int mi = 0; mi < 2; mi++)
#pragma unroll
            for (int nt = 0; nt < 4; nt++) {
                if (ks == 0) mmaf16z(c1[mi][nt], Qreg[0][mi], kf[nt]);
                else         mmaf16(c1[mi][nt], Qreg[ks][mi], kf[nt]);
            }
    }
}

// softmax over heads, fully packed fp16: 3 MUFU (f16x2) + 2 SHFL per (mi,nt).
// s = (e0+e2, e1+e3) then xor4/xor8 reduce; rinv broadcast-multiplies both pairs.
__device__ __forceinline__ void softmax_pack(float c1[2][4][4],
                                             uint32_t p01[2][4],
                                             uint32_t p23[2][4]) {
#pragma unroll
    for (int mi = 0; mi < 2; mi++)
#pragma unroll
        for (int nt = 0; nt < 4; nt++) {
            float* cc = c1[mi][nt];
            __half2 h01 = __floats2half2_rn(cc[0], cc[1]);
            __half2 h23 = __floats2half2_rn(cc[2], cc[3]);
            __half2 e01 = h2exp2(h01);
            __half2 e23 = h2exp2(h23);
            __half2 s = __hadd2(e01, e23);
            s = __hadd2(s, u2h(__shfl_xor_sync(0xffffffffu, h2u(s), 4)));
            s = __hadd2(s, u2h(__shfl_xor_sync(0xffffffffu, h2u(s), 8)));
            __half2 rinv = h2rcp(s);
            p01[mi][nt] = h2u(__hmul2(e01, rinv));
            p23[mi][nt] = h2u(__hmul2(e23, rinv));
        }
}

// phase-3: Oacc[mi][vt] += attn^T (A from packs) x V (B from smem)
__device__ __forceinline__ void phase3(const __half* Vs,
                                       const uint32_t p01[2][4],
                                       const uint32_t p23[2][4],
                                       float Oacc[2][8][4], int lane) {
#pragma unroll
    for (int ms = 0; ms < 2; ms++) {
        uint4 va = *(const uint4*)&Vs[ms * 1280 + lane * 40];
        uint4 vb = *(const uint4*)&Vs[ms * 1280 + lane * 40 + 8];
        uint4 vc = *(const uint4*)&Vs[ms * 1280 + lane * 40 + 16];
        uint4 vd = *(const uint4*)&Vs[ms * 1280 + lane * 40 + 24];
        uint32_t vf[8][2] = {{va.x, va.y}, {va.z, va.w}, {vb.x, vb.y}, {vb.z, vb.w},
                             {vc.x, vc.y}, {vc.z, vc.w}, {vd.x, vd.y}, {vd.z, vd.w}};
#pragma unroll
        for (int mi = 0; mi < 2; mi++) {
            uint32_t af[4] = {p01[mi][2 * ms], p23[mi][2 * ms],
                              p01[mi][2 * ms + 1], p23[mi][2 * ms + 1]};
#pragma unroll
            for (int vt = 0; vt < 8; vt++)
                mmaf16(Oacc[mi][vt], af, vf[vt]);
        }
    }
}

// ---------------- kernel 2: fused main (256 thr, 8 warps, 32 nh/warp) ----------------
__global__ void __launch_bounds__(256, 1) mqa_main(const float* __restrict__ x,
                                                   float* __restrict__ out) {
    extern __shared__ char smraw[];
    __half* smh = (__half*)smraw;

    const int b = blockIdx.y;
    const int n0 = blockIdx.x * 32;
    const int tid = threadIdx.x;
    const int lane = tid & 31;
    const int wgrp = tid >> 5;   // 0..7
    const int gid = lane >> 2;
    const int tig = lane & 3;

    const __half* Kg = g_K + b * 65536;
    const __half* Vg = g_V + b * 65536;

    const int dK = (tid >> 6) * 768 + ((tid & 63) >> 1) * 24 + (tid & 1) * 8;
    const int dV = V_OFF + (tid >> 7) * 1280 + ((tid >> 2) & 31) * 40 + (tid & 3) * 8;
    const uint32_t smem_u32 = (uint32_t)__cvta_generic_to_shared(smh);

#pragma unroll
    for (int s = 0; s < 4; s++) {
        cp16(smem_u32 + (s * STAGE_H + dK) * 2, Kg + s * 2048 + tid * 8);
        cp16(smem_u32 + (s * STAGE_H + dV) * 2, Vg + s * 2048 + tid * 8);
        CP_COMMIT();
    }

    // ---- prologue: Q projection (fp16 mma), then Q^T A-frags ----
    uint32_t Qreg[4][2][4];
    {
        __half* Xs = smh + XS_OFF;   // [32 n][264 d]
        const float* Xb = x + b * (D * NN);
#pragma unroll
        for (int i = 0; i < 32; i++) {
            int idx = tid + i * 256;
            int dd = idx >> 5, nn2 = idx & 31;
            Xs[nn2 * XSP + dd] = __float2half_rn(Xb[dd * NN + n0 + nn2]);
        }
        __syncthreads();

        float qa[4][4][4] = {};
        const __half* WqPw = g_WqP + wgrp * 16384;
#pragma unroll 4
        for (int kc = 0; kc < 16; kc++) {
            uint32_t bf[4][2];
#pragma unroll
            for (int ni = 0; ni < 4; ni++) {
                bf[ni][0] = *(const uint32_t*)&Xs[(ni * 8 + gid) * XSP + kc * 16 + 2 * tig];
                bf[ni][1] = *(const uint32_t*)&Xs[(ni * 8 + gid) * XSP + kc * 16 + 2 * tig + 8];
            }
#pragma unroll
            for (int mi = 0; mi < 4; mi++) {
                uint4 a = *(const uint4*)&WqPw[(kc * 4 + mi) * 256 + lane * 8];
#pragma unroll
                for (int ni = 0; ni < 4; ni++)
                    mmaf16(qa[mi][ni], (const uint32_t*)&a, bf[ni]);
            }
        }
        __syncthreads();   // Xs reads done

        __half* Qsm = smh + QSM_OFF;   // [nl32][h8][KP]
#pragma unroll
        for (int mi = 0; mi < 4; mi++)
#pragma unroll
            for (int ni = 0; ni < 4; ni++)
#pragma unroll
                for (int r = 0; r < 4; r++) {
                    int rk = wgrp * 64 + mi * 16 + gid + 8 * (r >> 1);
                    int nl = ni * 8 + 2 * tig + (r & 1);
                    Qsm[(nl * 8 + (rk & 7)) * KP + (rk >> 3)] =
                        __float2half_rn(qa[mi][ni][r]);
                }
        __syncthreads();

        // A-frags: rows (nl2, h) via gid bits; h>>2 selects reg pair
#pragma unroll
        for (int ks = 0; ks < 4; ks++)
#pragma unroll
            for (int mi = 0; mi < 2; mi++) {
                int nlb = wgrp * 4 + 2 * mi + (gid >> 2);
                int r01 = (nlb * 8 + (gid & 3)) * KP;
                int r23 = (nlb * 8 + (gid & 3) + 4) * KP;
                int kk = ks * 16 + 2 * tig;
                Qreg[ks][mi][0] = *(const uint32_t*)&Qsm[r01 + kk];
                Qreg[ks][mi][1] = *(const uint32_t*)&Qsm[r23 + kk];
                Qreg[ks][mi][2] = *(const uint32_t*)&Qsm[r01 + kk + 8];
                Qreg[ks][mi][3] = *(const uint32_t*)&Qsm[r23 + kk + 8];
            }
    }

    // ---- stage 0 ready; phase1(0) ----
    CP_WAIT(3);
    __syncthreads();

    float c1[2][4][4];
    phase1(smh, Qreg, c1, lane);

    float Oacc[2][8][4] = {};
    int sW = 4, sP1 = 1, sP3 = 0;

#pragma unroll 1
    for (int mch = 0; mch < 31; mch++) {
        CP_WAIT(2);
        __syncthreads();

        if (mch + 4 < 32) {
            cp16(smem_u32 + (sW * STAGE_H + dK) * 2, Kg + (mch + 4) * 2048 + tid * 8);
            cp16(smem_u32 + (sW * STAGE_H + dV) * 2, Vg + (mch + 4) * 2048 + tid * 8);
        }
        CP_COMMIT();

        uint32_t p01[2][4], p23[2][4];
        softmax_pack(c1, p01, p23);

        // phase1 of next chunk fills the softmax stall holes (c1 consumed)
        phase1(smh + sP1 * STAGE_H, Qreg, c1, lane);

        phase3(smh + sP3 * STAGE_H + V_OFF, p01, p23, Oacc, lane);

        sW = (sW == NSTAGE - 1) ? 0 : sW + 1;
        sP1 = (sP1 == NSTAGE - 1) ? 0 : sP1 + 1;
        sP3 = (sP3 == NSTAGE - 1) ? 0 : sP3 + 1;
    }

    // peeled final chunk
    {
        uint32_t p01[2][4], p23[2][4];
        softmax_pack(c1, p01, p23);
        phase3(smh + sP3 * STAGE_H + V_OFF, p01, p23, Oacc, lane);
    }
    CP_WAIT(0);
    __syncthreads();

    // ---- epilogue: stage O^T C-frags into Os[n][vh] ----
    __half* Os = smh;   // [32][OSP]
#pragma unroll
    for (int mi = 0; mi < 2; mi++) {
        int nl = wgrp * 4 + 2 * mi + (gid >> 2);
        int hb = gid & 3;
#pragma unroll
        for (int vt = 0; vt < 8; vt++) {
            int v0 = vt * 8 + 2 * tig;
            Os[nl * OSP + v0 * 8 + hb]           = __float2half_rn(Oacc[mi][vt][0]);
            Os[nl * OSP + (v0 + 1) * 8 + hb]     = __float2half_rn(Oacc[mi][vt][1]);
            Os[nl * OSP + v0 * 8 + hb + 4]       = __float2half_rn(Oacc[mi][vt][2]);
            Os[nl * OSP + (v0 + 1) * 8 + hb + 4] = __float2half_rn(Oacc[mi][vt][3]);
        }
    }
    __syncthreads();

    // ---- res = Wo @ O (fp16 mma, Wo A-frags from gmem/L2) ----
    float racc[2][4][4] = {};
    const __half* WoP = g_WoP + wgrp * 16384;
#pragma unroll 2
    for (int ks = 0; ks < 32; ks++) {
        uint4 a0 = *(const uint4*)&WoP[(ks * 2 + 0) * 256 + lane * 8];
        uint4 a1 = *(const uint4*)&WoP[(ks * 2 + 1) * 256 + lane * 8];
#pragma unroll
        for (int ni = 0; ni < 4; ni++) {
            uint32_t bf[2];
            bf[0] = *(const uint32_t*)&Os[(ni * 8 + gid) * OSP + ks * 16 + 2 * tig];
            bf[1] = *(const uint32_t*)&Os[(ni * 8 + gid) * OSP + ks * 16 + 2 * tig + 8];
            mmaf16(racc[0][ni], (const uint32_t*)&a0, bf);
            mmaf16(racc[1][ni], (const uint32_t*)&a1, bf);
        }
    }

    float* ob = out + b * (D * NN);
#pragma unroll
    for (int mi = 0; mi < 2; mi++)
#pragma unroll
        for (int ni = 0; ni < 4; ni++) {
            int d = wgrp * 32 + mi * 16 + gid;
            *(float2*)&ob[d * NN + n0 + ni * 8 + tig * 2] =
                make_float2(racc[mi][ni][0], racc[mi][ni][1]);
            *(float2*)&ob[(d + 8) * NN + n0 + ni * 8 + tig * 2] =
                make_float2(racc[mi][ni][2], racc[mi][ni][3]);
        }
}

// ---------------- launcher ----------------
extern "C" void kernel_launch(void* const* d_in, const int* in_sizes, int n_in,
                              void* d_out, int out_size) {
    const float* x     = (const float*)d_in[0];
    const float* value = (const float*)d_in[1];
    const float* Wq    = (const float*)d_in[2];
    const float* Wk    = (const float*)d_in[3];
    const float* Wv    = (const float*)d_in[4];
    const float* Wo    = (const float*)d_in[5];
    float* out = (float*)d_out;

    pack_weights<<<512, 256>>>(Wq, Wo);
    proj_kv<<<dim3(MM / 128, 1, B), 256, 32768>>>(Wk, Wv, value);

    cudaFuncSetAttribute(mqa_main, cudaFuncAttributeMaxDynamicSharedMemorySize, SMEM_BYTES);
    mqa_main<<<dim3(NN / 32, B), 256, SMEM_BYTES>>>(x, out);
}

// round 16
// speedup vs baseline: 1.3378x; 1.3083x over previous
#include <cuda_runtime.h>
#include <cuda_fp16.h>
#include <math.h>
#include <stdint.h>

#define B 8
#define D 256
#define NN 1024
#define MM 1024
#define KD 64
#define VD 64

#define NSTAGE 5
// smem halves: stage = K(3072, padded) + V(2560, padded)
#define STAGE_H 5632
#define V_OFF   3072
#define STAGES_H (NSTAGE * STAGE_H)     // 28160
#define XS_OFF  STAGES_H
#define XSP 264                          // main prologue Xs [32 n][264 d]
#define QSM_OFF STAGES_H
#define KP 68                            // Qsm [32 nl][8 h][68 k]
#define SMEM_HALFS (QSM_OFF + 32 * 8 * KP)   // 45568
#define SMEM_BYTES (SMEM_HALFS * 2)           // 91136
#define OSP 520                          // epilogue Os [32 n][520 vh] @ 0

#define XSP2 266                         // proj Xs [64 m][266 d] halfs

#define QSCALE 0.1803368801f   // 0.125 * log2(e)

__device__ __half g_WqP[512 * D];    // Wq A-frags fp16 (8-warp), pre-scaled
__device__ __half g_WkvP[128 * D];   // Wkv A-frags fp16 (8-warp, proj)
__device__ __half g_K[B * 32 * 2048];   // K as B-frags (k x m) per chunk
__device__ __half g_V[B * 32 * 2048];   // V as B-frags (m x v) per chunk
__device__ __half g_WoP[D * 512];    // Wo A-frags fp16 (8-warp)

__device__ __forceinline__ float ex2(float x) {
    float r; asm("ex2.approx.f32 %0, %1;" : "=f"(r) : "f"(x)); return r;
}
__device__ __forceinline__ float rcp(float x) {
    float r; asm("rcp.approx.f32 %0, %1;" : "=f"(r) : "f"(x)); return r;
}
__device__ __forceinline__ uint32_t packh2(float a, float b) {
    __half2 h = __floats2half2_rn(a, b);
    return *reinterpret_cast<uint32_t*>(&h);
}
__device__ __forceinline__ void mmaf16(float* c, const uint32_t* a, const uint32_t* b) {
    asm volatile(
        "mma.sync.aligned.m16n8k16.row.col.f32.f16.f16.f32 "
        "{%0,%1,%2,%3}, {%4,%5,%6,%7}, {%8,%9}, {%0,%1,%2,%3};\n"
        : "+f"(c[0]), "+f"(c[1]), "+f"(c[2]), "+f"(c[3])
        : "r"(a[0]), "r"(a[1]), "r"(a[2]), "r"(a[3]), "r"(b[0]), "r"(b[1]));
}
__device__ __forceinline__ void mmaf16z(float* c, const uint32_t* a, const uint32_t* b) {
    asm volatile(
        "mma.sync.aligned.m16n8k16.row.col.f32.f16.f16.f32 "
        "{%0,%1,%2,%3}, {%4,%5,%6,%7}, {%8,%9}, {%10,%10,%10,%10};\n"
        : "=f"(c[0]), "=f"(c[1]), "=f"(c[2]), "=f"(c[3])
        : "r"(a[0]), "r"(a[1]), "r"(a[2]), "r"(a[3]), "r"(b[0]), "r"(b[1]),
          "f"(0.0f));
}
__device__ __forceinline__ void cp16(uint32_t dst, const void* src) {
    asm volatile("cp.async.cg.shared.global [%0], [%1], 16;\n"
                 :: "r"(dst), "l"(src));
}
#define CP_COMMIT() asm volatile("cp.async.commit_group;\n" ::)
#define CP_WAIT(n)  asm volatile("cp.async.wait_group %0;\n" :: "n"(n))

// ---------------- kernel 0: pack Wq / Wkv / Wo fragments ----------------
__global__ void pack_weights(const float* __restrict__ Wq,
                             const float* __restrict__ Wk,
                             const float* __restrict__ Wv,
                             const float* __restrict__ Wo) {
    int i = blockIdx.x * blockDim.x + threadIdx.x;
    if (i < 512 * D) {   // WqP: [w8][kc16][mi4][lane32][r4][dlt2]
        int dlt = i & 1, r = (i >> 1) & 3, ln = (i >> 3) & 31;
        int mi = (i >> 8) & 3, kc = (i >> 10) & 15, w = (i >> 14) & 7;
        int g = ln >> 2, t = ln & 3;
        int rk = w * 64 + mi * 16 + g + 8 * (r & 1);
        int d = kc * 16 + 2 * t + dlt + 8 * (r >> 1);
        int kq = rk >> 3, h = rk & 7;
        g_WqP[i] = __float2half_rn(Wq[h * (D * KD) + d * KD + kq] * QSCALE);
    }
    if (i < 128 * D) {   // WkvP: [w8][ks16][lane32][r4][dlt2]
        int dlt = i & 1, r = (i >> 1) & 3, ln = (i >> 3) & 31;
        int ks = (i >> 8) & 15, w = (i >> 12) & 7;
        int g = ln >> 2, t = ln & 3;
        int row = w * 16 + g + 8 * (r & 1);
        int d = ks * 16 + 2 * t + dlt + 8 * (r >> 1);
        g_WkvP[i] = __float2half_rn(row < 64 ? Wk[d * KD + row]
                                             : Wv[d * VD + row - 64]);
    }
    if (i < D * 512) {   // WoP: [w8][ks32][mi2][lane32][r4][dlt2]
        int dlt = i & 1, r = (i >> 1) & 3, ln = (i >> 3) & 31;
        int mi = (i >> 8) & 1, ks = (i >> 9) & 31, w = (i >> 14) & 7;
        int g = ln >> 2, t = ln & 3;
        int d = w * 32 + mi * 16 + g + 8 * (r & 1);
        int vh = ks * 16 + 2 * t + dlt + 8 * (r >> 1);
        g_WoP[i] = __float2half_rn(Wo[d * 512 + vh]);
    }
}

// ---------------- kernel 1: K/V projection via fp16 tensor MMA ----------------
// grid (16, 1, 8): CTA computes P[128 r][64 m] = Wkv @ X[:, m0:m0+64)
__global__ void __launch_bounds__(256) proj_kv(const float* __restrict__ X) {
    extern __shared__ char smraw[];
    __half* Xs = (__half*)smraw;   // [64 m][266 d]
    const int b = blockIdx.z, m0 = blockIdx.x * 64;
    const int tid = threadIdx.x;
    const int lane = tid & 31, w = tid >> 5;
    const int gid = lane >> 2, tig = lane & 3;
    const float* Xb = X + b * (D * NN);

    // stage X tile as fp16 [m][d]
#pragma unroll
    for (int i = 0; i < 64; i++) {
        int idx = tid + i * 256;
        int dd = idx >> 6, mm = idx & 63;
        Xs[mm * XSP2 + dd] = __float2half_rn(Xb[dd * NN + m0 + mm]);
    }
    __syncthreads();

    float acc[8][4] = {};
    const __half* Ap = g_WkvP + w * 4096;
#pragma unroll 4
    for (int ks = 0; ks < 16; ks++) {
        uint4 a = *(const uint4*)&Ap[ks * 256 + lane * 8];
#pragma unroll
        for (int nt = 0; nt < 8; nt++) {
            uint32_t bf[2];
            bf[0] = *(const uint32_t*)&Xs[(nt * 8 + gid) * XSP2 + ks * 16 + 2 * tig];
            bf[1] = *(const uint32_t*)&Xs[(nt * 8 + gid) * XSP2 + ks * 16 + 2 * tig + 8];
            mmaf16(acc[nt], (const uint32_t*)&a, bf);
        }
    }
    __syncthreads();   // Xs fully consumed

    // scatter to fragment staging: K [2][2048] @0, V [2][2048] @4096
    __half* stg = (__half*)smraw;
#pragma unroll
    for (int nt = 0; nt < 8; nt++)
#pragma unroll
        for (int r = 0; r < 4; r++) {
            int row = w * 16 + gid + 8 * (r >> 1);
            int ml6 = nt * 8 + 2 * tig + (r & 1);
            __half v = __float2half_rn(acc[nt][r]);
            int mchl = ml6 >> 5, ml = ml6 & 31;
            if (row < 64) {   // K B-frag: K[k][m]
                int k = row;
                int nt2 = ml >> 3, gd = ml & 7;
                int ks2 = k >> 4, k16 = k & 15;
                int e = k16 >> 3, rem = k16 & 7, tg = rem >> 1, dlt = rem & 1;
                int ln = gd * 4 + tg;
                stg[mchl * 2048 + ks2 * 512 + ln * 16 + nt2 * 4 + e * 2 + dlt] = v;
            } else {          // V B-frag: V[m][v]
                int vv = row - 64;
                int ms = ml >> 4, m16 = ml & 15;
                int e = m16 >> 3, rem = m16 & 7, tg = rem >> 1, dlt = rem & 1;
                int vt = vv >> 3, gd = vv & 7;
                int ln = gd * 4 + tg;
                stg[4096 + mchl * 2048 + ms * 1024 + ln * 32 + vt * 4 + e * 2 + dlt] = v;
            }
        }
    __syncthreads();

    // coalesced copy out (2 chunks contiguous = 4096 halfs each of K and V)
    const uint4* s4 = (const uint4*)stg;
    uint4* dK4 = (uint4*)(g_K + (b * 32 + (m0 >> 5)) * 2048);
    uint4* dV4 = (uint4*)(g_V + (b * 32 + (m0 >> 5)) * 2048);
    dK4[tid] = s4[tid];
    dK4[tid + 256] = s4[tid + 256];
    dV4[tid] = s4[512 + tid];
    dV4[tid + 256] = s4[512 + tid + 256];
}

// phase-1: c1[mi][nt] = logits^T  (A = Q^T regs, B = K from smem)
__device__ __forceinline__ void phase1(const __half* Ks,
                                       const uint32_t Qreg[4][2][4],
                                       float c1[2][4][4], int lane) {
#pragma unroll
    for (int ks = 0; ks < 4; ks++) {
        uint4 ka = *(const uint4*)&Ks[ks * 768 + lane * 24];
        uint4 kb = *(const uint4*)&Ks[ks * 768 + lane * 24 + 8];
        uint32_t kf[4][2] = {{ka.x, ka.y}, {ka.z, ka.w}, {kb.x, kb.y}, {kb.z, kb.w}};
#pragma unroll
        for (int mi = 0; mi < 2; mi++)
#pragma unroll
            for (int nt = 0; nt < 4; nt++) {
                if (ks == 0) mmaf16z(c1[mi][nt], Qreg[0][mi], kf[nt]);
                else         mmaf16(c1[mi][nt], Qreg[ks][mi], kf[nt]);
            }
    }
}

// softmax over heads (fp32 MUFU, xor4/xor8 reductions), pack to half2
__device__ __forceinline__ void softmax_pack(float c1[2][4][4],
                                             uint32_t p01[2][4],
                                             uint32_t p23[2][4]) {
#pragma unroll
    for (int mi = 0; mi < 2; mi++)
#pragma unroll
        for (int nt = 0; nt < 4; nt++) {
            float* cc = c1[mi][nt];
            float e0 = ex2(cc[0]), e1 = ex2(cc[1]);
            float e2 = ex2(cc[2]), e3 = ex2(cc[3]);
            float s02 = e0 + e2, s13 = e1 + e3;
            s02 += __shfl_xor_sync(0xffffffffu, s02, 4);
            s02 += __shfl_xor_sync(0xffffffffu, s02, 8);
            s13 += __shfl_xor_sync(0xffffffffu, s13, 4);
            s13 += __shfl_xor_sync(0xffffffffu, s13, 8);
            float r02 = rcp(s02), r13 = rcp(s13);
            p01[mi][nt] = packh2(e0 * r02, e1 * r13);
            p23[mi][nt] = packh2(e2 * r02, e3 * r13);
        }
}

// phase-3: Oacc[mi][vt] += attn^T (A from packs) x V (B from smem)
__device__ __forceinline__ void phase3(const __half* Vs,
                                       const uint32_t p01[2][4],
                                       const uint32_t p23[2][4],
                                       float Oacc[2][8][4], int lane) {
#pragma unroll
    for (int ms = 0; ms < 2; ms++) {
        uint4 va = *(const uint4*)&Vs[ms * 1280 + lane * 40];
        uint4 vb = *(const uint4*)&Vs[ms * 1280 + lane * 40 + 8];
        uint4 vc = *(const uint4*)&Vs[ms * 1280 + lane * 40 + 16];
        uint4 vd = *(const uint4*)&Vs[ms * 1280 + lane * 40 + 24];
        uint32_t vf[8][2] = {{va.x, va.y}, {va.z, va.w}, {vb.x, vb.y}, {vb.z, vb.w},
                             {vc.x, vc.y}, {vc.z, vc.w}, {vd.x, vd.y}, {vd.z, vd.w}};
#pragma unroll
        for (int mi = 0; mi < 2; mi++) {
            uint32_t af[4] = {p01[mi][2 * ms], p23[mi][2 * ms],
                              p01[mi][2 * ms + 1], p23[mi][2 * ms + 1]};
#pragma unroll
            for (int vt = 0; vt < 8; vt++)
                mmaf16(Oacc[mi][vt], af, vf[vt]);
        }
    }
}

// ---------------- kernel 2: fused main (256 thr, 8 warps, 32 nh/warp) ----------------
__global__ void __launch_bounds__(256, 1) mqa_main(const float* __restrict__ x,
                                                   float* __restrict__ out) {
    extern __shared__ char smraw[];
    __half* smh = (__half*)smraw;

    const int b = blockIdx.y;
    const int n0 = blockIdx.x * 32;
    const int tid = threadIdx.x;
    const int lane = tid & 31;
    const int wgrp = tid >> 5;   // 0..7
    const int gid = lane >> 2;
    const int tig = lane & 3;

    const __half* Kg = g_K + b * 65536;
    const __half* Vg = g_V + b * 65536;

    const int dK = (tid >> 6) * 768 + ((tid & 63) >> 1) * 24 + (tid & 1) * 8;
    const int dV = V_OFF + (tid >> 7) * 1280 + ((tid >> 2) & 31) * 40 + (tid & 3) * 8;
    const uint32_t smem_u32 = (uint32_t)__cvta_generic_to_shared(smh);

#pragma unroll
    for (int s = 0; s < 4; s++) {
        cp16(smem_u32 + (s * STAGE_H + dK) * 2, Kg + s * 2048 + tid * 8);
        cp16(smem_u32 + (s * STAGE_H + dV) * 2, Vg + s * 2048 + tid * 8);
        CP_COMMIT();
    }

    // ---- prologue: Q projection (fp16 mma), then Q^T A-frags ----
    uint32_t Qreg[4][2][4];
    {
        __half* Xs = smh + XS_OFF;   // [32 n][264 d]
        const float* Xb = x + b * (D * NN);
#pragma unroll
        for (int i = 0; i < 32; i++) {
            int idx = tid + i * 256;
            int dd = idx >> 5, nn2 = idx & 31;
            Xs[nn2 * XSP + dd] = __float2half_rn(Xb[dd * NN + n0 + nn2]);
        }
        __syncthreads();

        float qa[4][4][4] = {};
        const __half* WqPw = g_WqP + wgrp * 16384;
#pragma unroll 4
        for (int kc = 0; kc < 16; kc++) {
            uint32_t bf[4][2];
#pragma unroll
            for (int ni = 0; ni < 4; ni++) {
                bf[ni][0] = *(const uint32_t*)&Xs[(ni * 8 + gid) * XSP + kc * 16 + 2 * tig];
                bf[ni][1] = *(const uint32_t*)&Xs[(ni * 8 + gid) * XSP + kc * 16 + 2 * tig + 8];
            }
#pragma unroll
            for (int mi = 0; mi < 4; mi++) {
                uint4 a = *(const uint4*)&WqPw[(kc * 4 + mi) * 256 + lane * 8];
#pragma unroll
                for (int ni = 0; ni < 4; ni++)
                    mmaf16(qa[mi][ni], (const uint32_t*)&a, bf[ni]);
            }
        }
        __syncthreads();   // Xs reads done

        __half* Qsm = smh + QSM_OFF;   // [nl32][h8][KP]
#pragma unroll
        for (int mi = 0; mi < 4; mi++)
#pragma unroll
            for (int ni = 0; ni < 4; ni++)
#pragma unroll
                for (int r = 0; r < 4; r++) {
                    int rk = wgrp * 64 + mi * 16 + gid + 8 * (r >> 1);
                    int nl = ni * 8 + 2 * tig + (r & 1);
                    Qsm[(nl * 8 + (rk & 7)) * KP + (rk >> 3)] =
                        __float2half_rn(qa[mi][ni][r]);
                }
        __syncthreads();

        // A-frags: rows (nl2, h) via gid bits; h>>2 selects reg pair
#pragma unroll
        for (int ks = 0; ks < 4; ks++)
#pragma unroll
            for (int mi = 0; mi < 2; mi++) {
                int nlb = wgrp * 4 + 2 * mi + (gid >> 2);
                int r01 = (nlb * 8 + (gid & 3)) * KP;
                int r23 = (nlb * 8 + (gid & 3) + 4) * KP;
                int kk = ks * 16 + 2 * tig;
                Qreg[ks][mi][0] = *(const uint32_t*)&Qsm[r01 + kk];
                Qreg[ks][mi][1] = *(const uint32_t*)&Qsm[r23 + kk];
                Qreg[ks][mi][2] = *(const uint32_t*)&Qsm[r01 + kk + 8];
                Qreg[ks][mi][3] = *(const uint32_t*)&Qsm[r23 + kk + 8];
            }
    }

    // ---- stage 0 ready; phase1(0) ----
    CP_WAIT(3);
    __syncthreads();

    float c1[2][4][4];
    phase1(smh, Qreg, c1, lane);

    float Oacc[2][8][4] = {};
    int sW = 4, sP1 = 1, sP3 = 0;

#pragma unroll 1
    for (int mch = 0; mch < 31; mch++) {
        CP_WAIT(2);
        __syncthreads();

        if (mch + 4 < 32) {
            cp16(smem_u32 + (sW * STAGE_H + dK) * 2, Kg + (mch + 4) * 2048 + tid * 8);
            cp16(smem_u32 + (sW * STAGE_H + dV) * 2, Vg + (mch + 4) * 2048 + tid * 8);
        }
        CP_COMMIT();

        uint32_t p01[2][4], p23[2][4];
        softmax_pack(c1, p01, p23);

        // phase1 of next chunk fills the softmax stall holes (c1 consumed)
        phase1(smh + sP1 * STAGE_H, Qreg, c1, lane);

        phase3(smh + sP3 * STAGE_H + V_OFF, p01, p23, Oacc, lane);

        sW = (sW == NSTAGE - 1) ? 0 : sW + 1;
        sP1 = (sP1 == NSTAGE - 1) ? 0 : sP1 + 1;
        sP3 = (sP3 == NSTAGE - 1) ? 0 : sP3 + 1;
    }

    // peeled final chunk
    {
        uint32_t p01[2][4], p23[2][4];
        softmax_pack(c1, p01, p23);
        phase3(smh + sP3 * STAGE_H + V_OFF, p01, p23, Oacc, lane);
    }
    CP_WAIT(0);
    __syncthreads();

    // ---- epilogue: stage O^T C-frags into Os[n][vh] ----
    __half* Os = smh;   // [32][OSP]
#pragma unroll
    for (int mi = 0; mi < 2; mi++) {
        int nl = wgrp * 4 + 2 * mi + (gid >> 2);
        int hb = gid & 3;
#pragma unroll
        for (int vt = 0; vt < 8; vt++) {
            int v0 = vt * 8 + 2 * tig;
            Os[nl * OSP + v0 * 8 + hb]           = __float2half_rn(Oacc[mi][vt][0]);
            Os[nl * OSP + (v0 + 1) * 8 + hb]     = __float2half_rn(Oacc[mi][vt][1]);
            Os[nl * OSP + v0 * 8 + hb + 4]       = __float2half_rn(Oacc[mi][vt][2]);
            Os[nl * OSP + (v0 + 1) * 8 + hb + 4] = __float2half_rn(Oacc[mi][vt][3]);
        }
    }
    __syncthreads();

    // ---- res = Wo @ O (fp16 mma, Wo A-frags from gmem/L2) ----
    float racc[2][4][4] = {};
    const __half* WoP = g_WoP + wgrp * 16384;
#pragma unroll 2
    for (int ks = 0; ks < 32; ks++) {
        uint4 a0 = *(const uint4*)&WoP[(ks * 2 + 0) * 256 + lane * 8];
        uint4 a1 = *(const uint4*)&WoP[(ks * 2 + 1) * 256 + lane * 8];
#pragma unroll
        for (int ni = 0; ni < 4; ni++) {
            uint32_t bf[2];
            bf[0] = *(const uint32_t*)&Os[(ni * 8 + gid) * OSP + ks * 16 + 2 * tig];
            bf[1] = *(const uint32_t*)&Os[(ni * 8 + gid) * OSP + ks * 16 + 2 * tig + 8];
            mmaf16(racc[0][ni], (const uint32_t*)&a0, bf);
            mmaf16(racc[1][ni], (const uint32_t*)&a1, bf);
        }
    }

    float* ob = out + b * (D * NN);
#pragma unroll
    for (int mi = 0; mi < 2; mi++)
#pragma unroll
        for (int ni = 0; ni < 4; ni++) {
            int d = wgrp * 32 + mi * 16 + gid;
            *(float2*)&ob[d * NN + n0 + ni * 8 + tig * 2] =
                make_float2(racc[mi][ni][0], racc[mi][ni][1]);
            *(float2*)&ob[(d + 8) * NN + n0 + ni * 8 + tig * 2] =
                make_float2(racc[mi][ni][2], racc[mi][ni][3]);
        }
}

// ---------------- launcher ----------------
extern "C" void kernel_launch(void* const* d_in, const int* in_sizes, int n_in,
                              void* d_out, int out_size) {
    const float* x     = (const float*)d_in[0];
    const float* value = (const float*)d_in[1];
    const float* Wq    = (const float*)d_in[2];
    const float* Wk    = (const float*)d_in[3];
    const float* Wv    = (const float*)d_in[4];
    const float* Wo    = (const float*)d_in[5];
    float* out = (float*)d_out;

    pack_weights<<<512, 256>>>(Wq, Wk, Wv, Wo);
    proj_kv<<<dim3(16, 1, B), 256, 64 * XSP2 * 2>>>(value);

    cudaFuncSetAttribute(mqa_main, cudaFuncAttributeMaxDynamicSharedMemorySize, SMEM_BYTES);
    mqa_main<<<dim3(NN / 32, B), 256, SMEM_BYTES>>>(x, out);
}

// round 17
// speedup vs baseline: 1.3622x; 1.0183x over previous
#include <cuda_runtime.h>
#include <cuda_fp16.h>
#include <math.h>
#include <stdint.h>

#define B 8
#define D 256
#define NN 1024
#define MM 1024
#define KD 64
#define VD 64

#define NSTAGE 5
// smem halves: stage = K(3072, padded) + V(2560, padded)
#define STAGE_H 5632
#define V_OFF   3072
#define STAGES_H (NSTAGE * STAGE_H)     // 28160
#define XS_OFF  STAGES_H
#define XSP 264                          // main prologue Xs [16 n][264 d]
#define QSM_OFF STAGES_H
#define KP 68                            // Qsm [16 nl][8 h][68 k]
#define SMEM_HALFS (QSM_OFF + 16 * 8 * KP)   // 36864
#define SMEM_BYTES (SMEM_HALFS * 2)           // 73728 (2 CTAs/SM fit)
#define OSP 520                          // epilogue Os [16 n][520 vh] @ 0

#define XSP2 266                         // proj Xs [64 m][266 d] halfs

#define QSCALE 0.1803368801f   // 0.125 * log2(e)

__device__ __half g_WqP[512 * D];    // Wq A-frags fp16 (8-warp), pre-scaled
__device__ __half g_WkvP[128 * D];   // Wkv A-frags fp16 (proj)
__device__ __half g_K[B * 32 * 2048];   // K as B-frags (k x m) per chunk
__device__ __half g_V[B * 32 * 2048];   // V as B-frags (m x v) per chunk
__device__ __half g_WoP[D * 512];    // Wo A-frags fp16 (8-warp)

__device__ __forceinline__ float ex2(float x) {
    float r; asm("ex2.approx.f32 %0, %1;" : "=f"(r) : "f"(x)); return r;
}
__device__ __forceinline__ float rcp(float x) {
    float r; asm("rcp.approx.f32 %0, %1;" : "=f"(r) : "f"(x)); return r;
}
__device__ __forceinline__ uint32_t packh2(float a, float b) {
    __half2 h = __floats2half2_rn(a, b);
    return *reinterpret_cast<uint32_t*>(&h);
}
__device__ __forceinline__ void mmaf16(float* c, const uint32_t* a, const uint32_t* b) {
    asm volatile(
        "mma.sync.aligned.m16n8k16.row.col.f32.f16.f16.f32 "
        "{%0,%1,%2,%3}, {%4,%5,%6,%7}, {%8,%9}, {%0,%1,%2,%3};\n"
        : "+f"(c[0]), "+f"(c[1]), "+f"(c[2]), "+f"(c[3])
        : "r"(a[0]), "r"(a[1]), "r"(a[2]), "r"(a[3]), "r"(b[0]), "r"(b[1]));
}
__device__ __forceinline__ void mmaf16z(float* c, const uint32_t* a, const uint32_t* b) {
    asm volatile(
        "mma.sync.aligned.m16n8k16.row.col.f32.f16.f16.f32 "
        "{%0,%1,%2,%3}, {%4,%5,%6,%7}, {%8,%9}, {%10,%10,%10,%10};\n"
        : "=f"(c[0]), "=f"(c[1]), "=f"(c[2]), "=f"(c[3])
        : "r"(a[0]), "r"(a[1]), "r"(a[2]), "r"(a[3]), "r"(b[0]), "r"(b[1]),
          "f"(0.0f));
}
__device__ __forceinline__ void cp16(uint32_t dst, const void* src) {
    asm volatile("cp.async.cg.shared.global [%0], [%1], 16;\n"
                 :: "r"(dst), "l"(src));
}
#define CP_COMMIT() asm volatile("cp.async.commit_group;\n" ::)
#define CP_WAIT(n)  asm volatile("cp.async.wait_group %0;\n" :: "n"(n))

// ---------------- kernel 0: pack Wq / Wkv / Wo fragments ----------------
__global__ void pack_weights(const float* __restrict__ Wq,
                             const float* __restrict__ Wk,
                             const float* __restrict__ Wv,
                             const float* __restrict__ Wo) {
    int i = blockIdx.x * blockDim.x + threadIdx.x;
    if (i < 512 * D) {   // WqP: [w8][kc16][mi4][lane32][r4][dlt2]
        int dlt = i & 1, r = (i >> 1) & 3, ln = (i >> 3) & 31;
        int mi = (i >> 8) & 3, kc = (i >> 10) & 15, w = (i >> 14) & 7;
        int g = ln >> 2, t = ln & 3;
        int rk = w * 64 + mi * 16 + g + 8 * (r & 1);
        int d = kc * 16 + 2 * t + dlt + 8 * (r >> 1);
        int kq = rk >> 3, h = rk & 7;
        g_WqP[i] = __float2half_rn(Wq[h * (D * KD) + d * KD + kq] * QSCALE);
    }
    if (i < 128 * D) {   // WkvP: [w8][ks16][lane32][r4][dlt2]
        int dlt = i & 1, r = (i >> 1) & 3, ln = (i >> 3) & 31;
        int ks = (i >> 8) & 15, w = (i >> 12) & 7;
        int g = ln >> 2, t = ln & 3;
        int row = w * 16 + g + 8 * (r & 1);
        int d = ks * 16 + 2 * t + dlt + 8 * (r >> 1);
        g_WkvP[i] = __float2half_rn(row < 64 ? Wk[d * KD + row]
                                             : Wv[d * VD + row - 64]);
    }
    if (i < D * 512) {   // WoP: [w8][ks32][mi2][lane32][r4][dlt2]
        int dlt = i & 1, r = (i >> 1) & 3, ln = (i >> 3) & 31;
        int mi = (i >> 8) & 1, ks = (i >> 9) & 31, w = (i >> 14) & 7;
        int g = ln >> 2, t = ln & 3;
        int d = w * 32 + mi * 16 + g + 8 * (r & 1);
        int vh = ks * 16 + 2 * t + dlt + 8 * (r >> 1);
        g_WoP[i] = __float2half_rn(Wo[d * 512 + vh]);
    }
}

// ---------------- kernel 1: K/V projection via fp16 tensor MMA ----------------
__global__ void __launch_bounds__(256) proj_kv(const float* __restrict__ X) {
    extern __shared__ char smraw[];
    __half* Xs = (__half*)smraw;   // [64 m][266 d]
    const int b = blockIdx.z, m0 = blockIdx.x * 64;
    const int tid = threadIdx.x;
    const int lane = tid & 31, w = tid >> 5;
    const int gid = lane >> 2, tig = lane & 3;
    const float* Xb = X + b * (D * NN);

#pragma unroll
    for (int i = 0; i < 64; i++) {
        int idx = tid + i * 256;
        int dd = idx >> 6, mm = idx & 63;
        Xs[mm * XSP2 + dd] = __float2half_rn(Xb[dd * NN + m0 + mm]);
    }
    __syncthreads();

    float acc[8][4] = {};
    const __half* Ap = g_WkvP + w * 4096;
#pragma unroll 4
    for (int ks = 0; ks < 16; ks++) {
        uint4 a = *(const uint4*)&Ap[ks * 256 + lane * 8];
#pragma unroll
        for (int nt = 0; nt < 8; nt++) {
            uint32_t bf[2];
            bf[0] = *(const uint32_t*)&Xs[(nt * 8 + gid) * XSP2 + ks * 16 + 2 * tig];
            bf[1] = *(const uint32_t*)&Xs[(nt * 8 + gid) * XSP2 + ks * 16 + 2 * tig + 8];
            mmaf16(acc[nt], (const uint32_t*)&a, bf);
        }
    }
    __syncthreads();

    __half* stg = (__half*)smraw;
#pragma unroll
    for (int nt = 0; nt < 8; nt++)
#pragma unroll
        for (int r = 0; r < 4; r++) {
            int row = w * 16 + gid + 8 * (r >> 1);
            int ml6 = nt * 8 + 2 * tig + (r & 1);
            __half v = __float2half_rn(acc[nt][r]);
            int mchl = ml6 >> 5, ml = ml6 & 31;
            if (row < 64) {
                int k = row;
                int nt2 = ml >> 3, gd = ml & 7;
                int ks2 = k >> 4, k16 = k & 15;
                int e = k16 >> 3, rem = k16 & 7, tg = rem >> 1, dlt = rem & 1;
                int ln = gd * 4 + tg;
                stg[mchl * 2048 + ks2 * 512 + ln * 16 + nt2 * 4 + e * 2 + dlt] = v;
            } else {
                int vv = row - 64;
                int ms = ml >> 4, m16 = ml & 15;
                int e = m16 >> 3, rem = m16 & 7, tg = rem >> 1, dlt = rem & 1;
                int vt = vv >> 3, gd = vv & 7;
                int ln = gd * 4 + tg;
                stg[4096 + mchl * 2048 + ms * 1024 + ln * 32 + vt * 4 + e * 2 + dlt] = v;
            }
        }
    __syncthreads();

    const uint4* s4 = (const uint4*)stg;
    uint4* dK4 = (uint4*)(g_K + (b * 32 + (m0 >> 5)) * 2048);
    uint4* dV4 = (uint4*)(g_V + (b * 32 + (m0 >> 5)) * 2048);
    dK4[tid] = s4[tid];
    dK4[tid + 256] = s4[tid + 256];
    dV4[tid] = s4[512 + tid];
    dV4[tid + 256] = s4[512 + tid + 256];
}

// phase-1: c1[nt] = logits^T  (A = Q^T regs 16 cols, B = K from smem)
__device__ __forceinline__ void phase1(const __half* Ks,
                                       const uint32_t Qreg[4][4],
                                       float c1[4][4], int lane) {
#pragma unroll
    for (int ks = 0; ks < 4; ks++) {
        uint4 ka = *(const uint4*)&Ks[ks * 768 + lane * 24];
        uint4 kb = *(const uint4*)&Ks[ks * 768 + lane * 24 + 8];
        uint32_t kf[4][2] = {{ka.x, ka.y}, {ka.z, ka.w}, {kb.x, kb.y}, {kb.z, kb.w}};
#pragma unroll
        for (int nt = 0; nt < 4; nt++) {
            if (ks == 0) mmaf16z(c1[nt], Qreg[0], kf[nt]);
            else         mmaf16(c1[nt], Qreg[ks], kf[nt]);
        }
    }
}

// softmax over heads (fp32 MUFU, xor4/xor8 reductions), pack to half2
__device__ __forceinline__ void softmax_pack(float c1[4][4],
                                             uint32_t p01[4], uint32_t p23[4]) {
#pragma unroll
    for (int nt = 0; nt < 4; nt++) {
        float* cc = c1[nt];
        float e0 = ex2(cc[0]), e1 = ex2(cc[1]);
        float e2 = ex2(cc[2]), e3 = ex2(cc[3]);
        float s02 = e0 + e2, s13 = e1 + e3;
        s02 += __shfl_xor_sync(0xffffffffu, s02, 4);
        s02 += __shfl_xor_sync(0xffffffffu, s02, 8);
        s13 += __shfl_xor_sync(0xffffffffu, s13, 4);
        s13 += __shfl_xor_sync(0xffffffffu, s13, 8);
        float r02 = rcp(s02), r13 = rcp(s13);
        p01[nt] = packh2(e0 * r02, e1 * r13);
        p23[nt] = packh2(e2 * r02, e3 * r13);
    }
}

// phase-3: Oacc[vt] += attn^T (A from packs) x V (B from smem)
__device__ __forceinline__ void phase3(const __half* Vs,
                                       const uint32_t p01[4], const uint32_t p23[4],
                                       float Oacc[8][4], int lane) {
#pragma unroll
    for (int ms = 0; ms < 2; ms++) {
        uint4 va = *(const uint4*)&Vs[ms * 1280 + lane * 40];
        uint4 vb = *(const uint4*)&Vs[ms * 1280 + lane * 40 + 8];
        uint4 vc = *(const uint4*)&Vs[ms * 1280 + lane * 40 + 16];
        uint4 vd = *(const uint4*)&Vs[ms * 1280 + lane * 40 + 24];
        uint32_t vf[8][2] = {{va.x, va.y}, {va.z, va.w}, {vb.x, vb.y}, {vb.z, vb.w},
                             {vc.x, vc.y}, {vc.z, vc.w}, {vd.x, vd.y}, {vd.z, vd.w}};
        uint32_t af[4] = {p01[2 * ms], p23[2 * ms], p01[2 * ms + 1], p23[2 * ms + 1]};
#pragma unroll
        for (int vt = 0; vt < 8; vt++)
            mmaf16(Oacc[vt], af, vf[vt]);
    }
}

// ---------------- kernel 2: fused main (256 thr, 8 warps, 16 nh/warp, 2 CTA/SM) ----------------
__global__ void __launch_bounds__(256, 2) mqa_main(const float* __restrict__ x,
                                                   float* __restrict__ out) {
    extern __shared__ char smraw[];
    __half* smh = (__half*)smraw;

    const int b = blockIdx.y;
    const int n0 = blockIdx.x * 16;
    const int tid = threadIdx.x;
    const int lane = tid & 31;
    const int wgrp = tid >> 5;   // 0..7
    const int gid = lane >> 2;
    const int tig = lane & 3;

    const __half* Kg = g_K + b * 65536;
    const __half* Vg = g_V + b * 65536;

    const int dK = (tid >> 6) * 768 + ((tid & 63) >> 1) * 24 + (tid & 1) * 8;
    const int dV = V_OFF + (tid >> 7) * 1280 + ((tid >> 2) & 31) * 40 + (tid & 3) * 8;
    const uint32_t smem_u32 = (uint32_t)__cvta_generic_to_shared(smh);

#pragma unroll
    for (int s = 0; s < 4; s++) {
        cp16(smem_u32 + (s * STAGE_H + dK) * 2, Kg + s * 2048 + tid * 8);
        cp16(smem_u32 + (s * STAGE_H + dV) * 2, Vg + s * 2048 + tid * 8);
        CP_COMMIT();
    }

    // ---- prologue: Q projection (fp16 mma), then Q^T A-frags ----
    uint32_t Qreg[4][4];
    {
        __half* Xs = smh + XS_OFF;   // [16 n][264 d]
        const float* Xb = x + b * (D * NN);
#pragma unroll
        for (int i = 0; i < 16; i++) {
            int idx = tid + i * 256;
            int dd = idx >> 4, nn2 = idx & 15;
            Xs[nn2 * XSP + dd] = __float2half_rn(Xb[dd * NN + n0 + nn2]);
        }
        __syncthreads();

        float qa[4][2][4] = {};
        const __half* WqPw = g_WqP + wgrp * 16384;
#pragma unroll 4
        for (int kc = 0; kc < 16; kc++) {
            uint32_t bf[2][2];
#pragma unroll
            for (int ni = 0; ni < 2; ni++) {
                bf[ni][0] = *(const uint32_t*)&Xs[(ni * 8 + gid) * XSP + kc * 16 + 2 * tig];
                bf[ni][1] = *(const uint32_t*)&Xs[(ni * 8 + gid) * XSP + kc * 16 + 2 * tig + 8];
            }
#pragma unroll
            for (int mi = 0; mi < 4; mi++) {
                uint4 a = *(const uint4*)&WqPw[(kc * 4 + mi) * 256 + lane * 8];
#pragma unroll
                for (int ni = 0; ni < 2; ni++)
                    mmaf16(qa[mi][ni], (const uint32_t*)&a, bf[ni]);
            }
        }
        __syncthreads();   // Xs reads done

        __half* Qsm = smh + QSM_OFF;   // [16 nl][8 h][KP]
#pragma unroll
        for (int mi = 0; mi < 4; mi++)
#pragma unroll
            for (int ni = 0; ni < 2; ni++)
#pragma unroll
                for (int r = 0; r < 4; r++) {
                    int rk = wgrp * 64 + mi * 16 + gid + 8 * (r >> 1);
                    int nl = ni * 8 + 2 * tig + (r & 1);
                    Qsm[(nl * 8 + (rk & 7)) * KP + (rk >> 3)] =
                        __float2half_rn(qa[mi][ni][r]);
                }
        __syncthreads();

        // A-frags: warp cols = nl {wgrp*2 + (gid>>2)}, h = gid&3 (+4 for c2/c3)
        int nlb = wgrp * 2 + (gid >> 2);
        int r01 = (nlb * 8 + (gid & 3)) * KP;
        int r23 = (nlb * 8 + (gid & 3) + 4) * KP;
#pragma unroll
        for (int ks = 0; ks < 4; ks++) {
            int kk = ks * 16 + 2 * tig;
            Qreg[ks][0] = *(const uint32_t*)&Qsm[r01 + kk];
            Qreg[ks][1] = *(const uint32_t*)&Qsm[r23 + kk];
            Qreg[ks][2] = *(const uint32_t*)&Qsm[r01 + kk + 8];
            Qreg[ks][3] = *(const uint32_t*)&Qsm[r23 + kk + 8];
        }
    }

    // ---- stage 0 ready; phase1(0) ----
    CP_WAIT(3);
    __syncthreads();

    float c1[4][4];
    phase1(smh, Qreg, c1, lane);

    float Oacc[8][4] = {};
    int sW = 4, sP1 = 1, sP3 = 0;

#pragma unroll 1
    for (int mch = 0; mch < 31; mch++) {
        CP_WAIT(2);
        __syncthreads();

        if (mch + 4 < 32) {
            cp16(smem_u32 + (sW * STAGE_H + dK) * 2, Kg + (mch + 4) * 2048 + tid * 8);
            cp16(smem_u32 + (sW * STAGE_H + dV) * 2, Vg + (mch + 4) * 2048 + tid * 8);
        }
        CP_COMMIT();

        uint32_t p01[4], p23[4];
        softmax_pack(c1, p01, p23);

        // phase1 of next chunk fills the softmax stall holes (c1 consumed)
        phase1(smh + sP1 * STAGE_H, Qreg, c1, lane);

        phase3(smh + sP3 * STAGE_H + V_OFF, p01, p23, Oacc, lane);

        sW = (sW == NSTAGE - 1) ? 0 : sW + 1;
        sP1 = (sP1 == NSTAGE - 1) ? 0 : sP1 + 1;
        sP3 = (sP3 == NSTAGE - 1) ? 0 : sP3 + 1;
    }

    // peeled final chunk
    {
        uint32_t p01[4], p23[4];
        softmax_pack(c1, p01, p23);
        phase3(smh + sP3 * STAGE_H + V_OFF, p01, p23, Oacc, lane);
    }
    CP_WAIT(0);
    __syncthreads();

    // ---- epilogue: stage O^T C-frags into Os[n][vh] ----
    __half* Os = smh;   // [16][OSP]
    {
        int nl = wgrp * 2 + (gid >> 2);
        int hb = gid & 3;
#pragma unroll
        for (int vt = 0; vt < 8; vt++) {
            int v0 = vt * 8 + 2 * tig;
            Os[nl * OSP + v0 * 8 + hb]           = __float2half_rn(Oacc[vt][0]);
            Os[nl * OSP + (v0 + 1) * 8 + hb]     = __float2half_rn(Oacc[vt][1]);
            Os[nl * OSP + v0 * 8 + hb + 4]       = __float2half_rn(Oacc[vt][2]);
            Os[nl * OSP + (v0 + 1) * 8 + hb + 4] = __float2half_rn(Oacc[vt][3]);
        }
    }
    __syncthreads();

    // ---- res = Wo @ O (fp16 mma, Wo A-frags from gmem/L2) ----
    float racc[2][2][4] = {};
    const __half* WoP = g_WoP + wgrp * 16384;
#pragma unroll 4
    for (int ks = 0; ks < 32; ks++) {
        uint4 a0 = *(const uint4*)&WoP[(ks * 2 + 0) * 256 + lane * 8];
        uint4 a1 = *(const uint4*)&WoP[(ks * 2 + 1) * 256 + lane * 8];
#pragma unroll
        for (int ni = 0; ni < 2; ni++) {
            uint32_t bf[2];
            bf[0] = *(const uint32_t*)&Os[(ni * 8 + gid) * OSP + ks * 16 + 2 * tig];
            bf[1] = *(const uint32_t*)&Os[(ni * 8 + gid) * OSP + ks * 16 + 2 * tig + 8];
            mmaf16(racc[0][ni], (const uint32_t*)&a0, bf);
            mmaf16(racc[1][ni], (const uint32_t*)&a1, bf);
        }
    }

    float* ob = out + b * (D * NN);
#pragma unroll
    for (int mi = 0; mi < 2; mi++)
#pragma unroll
        for (int ni = 0; ni < 2; ni++) {
            int d = wgrp * 32 + mi * 16 + gid;
            *(float2*)&ob[d * NN + n0 + ni * 8 + tig * 2] =
                make_float2(racc[mi][ni][0], racc[mi][ni][1]);
            *(float2*)&ob[(d + 8) * NN + n0 + ni * 8 + tig * 2] =
                make_float2(racc[mi][ni][2], racc[mi][ni][3]);
        }
}

// ---------------- launcher ----------------
extern "C" void kernel_launch(void* const* d_in, const int* in_sizes, int n_in,
                              void* d_out, int out_size) {
    const float* x     = (const float*)d_in[0];
    const float* value = (const float*)d_in[1];
    const float* Wq    = (const float*)d_in[2];
    const float* Wk    = (const float*)d_in[3];
    const float* Wv    = (const float*)d_in[4];
    const float* Wo    = (const float*)d_in[5];
    float* out = (float*)d_out;

    pack_weights<<<512, 256>>>(Wq, Wk, Wv, Wo);
    proj_kv<<<dim3(16, 1, B), 256, 64 * XSP2 * 2>>>(value);

    cudaFuncSetAttribute(mqa_main, cudaFuncAttributeMaxDynamicSharedMemorySize, SMEM_BYTES);
    mqa_main<<<dim3(NN / 16, B), 256, SMEM_BYTES>>>(x, out);
}